// round 8
// baseline (speedup 1.0000x reference)
#include <cuda_runtime.h>
#include <cuda_bf16.h>
#include <cstdint>

// VectorQuantizer: TF32 mma.sync screen (e2 folded into augmented GEMM) +
// provable-margin exact rescore. B=32, D=64, T=8192, K=512.

#define BB 32
#define DD 64
#define TT 8192
#define KK 512
#define NTOK (BB * TT)
#define TILE_M 128
#define NTILES (NTOK / TILE_M)      // 2048
#define TILES_PER_B (TT / TILE_M)   // 64
#define NTHREADS 256
#define GRIDX 152
#define ARRSZ ((long long)BB * DD * TT)
#define MARGIN_V 5e-5f              // v-scale; dist-scale margin = 1e-4
#define FINF 3.402823466e38f

#define STRF 76                     // floats per row (conflict-free LDS)
#define KAUG 9                      // 8 real k-steps + 1 augmented

// smem byte offsets
#define OFF_QN     0
#define OFF_REDF   32        // 8 f
#define OFF_REDK   64        // 8 i
#define OFF_E2     128       // 512 f -> 2176
#define OFF_X2     2176      // 128 f -> 2688
#define OFF_WIN    2688      // 128 i -> 3200
#define OFF_QUE    3200      // 128 i -> 3712
#define OFF_A      3840      // 128*76*4 = 38912 -> 42752
#define OFF_QS     OFF_A     // overlay: 64*128*4 = 32768 <= 38912
#define OFF_B      42752     // 512*76*4 = 155648 -> 198400
#define SMEM_TOTAL 198400

__device__ __forceinline__ uint32_t f2tf32(float v) {
    uint32_t u;
    asm("cvt.rna.tf32.f32 %0, %1;" : "=r"(u) : "f"(v));
    return u;
}
__device__ __forceinline__ void mma_tf32(float* c, const uint32_t* a, uint32_t b0, uint32_t b1) {
    asm volatile("mma.sync.aligned.m16n8k8.row.col.f32.tf32.tf32.f32 "
                 "{%0,%1,%2,%3}, {%4,%5,%6,%7}, {%8,%9}, {%0,%1,%2,%3};"
                 : "+f"(c[0]), "+f"(c[1]), "+f"(c[2]), "+f"(c[3])
                 : "r"(a[0]), "r"(a[1]), "r"(a[2]), "r"(a[3]), "r"(b0), "r"(b1));
}
// top-2 MAX tracker (ascending k, strict > keeps first index)
__device__ __forceinline__ void top2max(float v, int k, float& m1, float& m2, int& i1) {
    if (v > m1) { m2 = m1; m1 = v; i1 = k; }
    else if (v > m2) { m2 = v; }
}

extern __shared__ __align__(1024) char smem[];

__global__ void __launch_bounds__(NTHREADS, 1)
vq_tf32_kernel(const float* __restrict__ x,
               const float* __restrict__ emb,
               float* __restrict__ out) {
    const int tid  = threadIdx.x;
    const int wid  = tid >> 5;
    const int lane = tid & 31;
    const int lg   = lane >> 2;     // 0..7
    const int l4   = lane & 3;      // 0..3

    float*    s_e2  = (float*)(smem + OFF_E2);
    float*    s_x2  = (float*)(smem + OFF_X2);
    int*      s_win = (int*)(smem + OFF_WIN);
    int*      s_que = (int*)(smem + OFF_QUE);
    float*    s_redf = (float*)(smem + OFF_REDF);
    int*      s_redk = (int*)(smem + OFF_REDK);
    int*      s_qn  = (int*)(smem + OFF_QN);
    uint32_t* s_a   = (uint32_t*)(smem + OFF_A);
    uint32_t* s_b   = (uint32_t*)(smem + OFF_B);
    float*    q_s   = (float*)(smem + OFF_QS);

    // ---- Prologue: codebook -> exact e2 chain + tf32 rows (aug col = -e2/2) ----
    for (int r = tid; r < KK; r += NTHREADS) {
        float ev[DD];
        const float4* er = (const float4*)(emb + r * DD);
        #pragma unroll
        for (int g = 0; g < DD / 4; g++) {
            float4 v = er[g];
            ev[g*4+0] = v.x; ev[g*4+1] = v.y; ev[g*4+2] = v.z; ev[g*4+3] = v.w;
        }
        float s = 0.0f;
        #pragma unroll
        for (int d = 0; d < DD; d++) s = __fadd_rn(s, __fmul_rn(ev[d], ev[d]));
        s_e2[r] = s;
        uint32_t* brow = s_b + r * STRF;
        #pragma unroll
        for (int d = 0; d < DD; d++) brow[d] = f2tf32(ev[d]);
        brow[64] = f2tf32(-0.5f * s);
        #pragma unroll
        for (int d = 65; d < 72; d++) brow[d] = 0u;
    }

    float* o_st = out;
    float* o_q  = out + ARRSZ;

    for (int tile = blockIdx.x; tile < NTILES; tile += GRIDX) {
        const int b  = tile / TILES_PER_B;
        const int t0 = (tile % TILES_PER_B) * TILE_M;
        const float* xb = x + (long long)b * DD * TT + t0;
        const long long obase = (long long)b * DD * TT;

        // ---- Phase A: x load (threads 0..127), exact x2, tf32 rows + aug=1 ----
        if (tid == 0) *s_qn = 0;
        if (tid < TILE_M) {
            const int tt = tid;
            float xv[DD];
            #pragma unroll
            for (int d = 0; d < DD; d++) xv[d] = xb[(long long)d * TT + tt];
            float s = 0.0f;
            #pragma unroll
            for (int d = 0; d < DD; d++) s = __fadd_rn(s, __fmul_rn(xv[d], xv[d]));
            s_x2[tt] = s;
            uint32_t* arow = s_a + tt * STRF;
            #pragma unroll
            for (int d = 0; d < DD; d++) arow[d] = f2tf32(xv[d]);
            arow[64] = 0x3F800000u;   // 1.0f (exact in tf32)
            #pragma unroll
            for (int d = 65; d < 72; d++) arow[d] = 0u;
        }
        __syncthreads();

        // ---- Phase B: screen. warp w: tokens [16w,16w+16) x all 512 codes ----
        {
            const int m0 = wid * 16;
            // A fragments: 9 k-steps x 4 regs
            uint32_t a[KAUG][4];
            const uint32_t* A0 = s_a + (m0 + lg) * STRF;
            #pragma unroll
            for (int kk = 0; kk < KAUG; kk++) {
                const int c = kk * 8 + l4;
                a[kk][0] = A0[c];
                a[kk][1] = A0[8 * STRF + c];
                a[kk][2] = A0[c + 4];
                a[kk][3] = A0[8 * STRF + c + 4];
            }

            float m1a = -FINF, m2a = -FINF, m1b = -FINF, m2b = -FINF;
            int   i1a = 0, i1b = 0;

            #pragma unroll 2
            for (int pt = 0; pt < 32; pt++) {
                const int cb = pt * 16;
                const uint32_t* B0 = s_b + (cb + lg) * STRF + l4;
                const uint32_t* B1 = B0 + 8 * STRF;
                float acc0[4] = {0.f, 0.f, 0.f, 0.f};
                float acc1[4] = {0.f, 0.f, 0.f, 0.f};
                #pragma unroll
                for (int kk = 0; kk < KAUG; kk++) {
                    uint32_t b0 = B0[kk * 8];
                    uint32_t b1 = B0[kk * 8 + 4];
                    uint32_t b2 = B1[kk * 8];
                    uint32_t b3 = B1[kk * 8 + 4];
                    mma_tf32(acc0, a[kk], b0, b1);
                    mma_tf32(acc1, a[kk], b2, b3);
                }
                // acc = v = xe - e2/2 ; argmax v == argmin dist
                const int k0 = cb + 2 * l4;
                const int k1 = cb + 8 + 2 * l4;
                top2max(acc0[0], k0,     m1a, m2a, i1a);
                top2max(acc0[1], k0 + 1, m1a, m2a, i1a);
                top2max(acc0[2], k0,     m1b, m2b, i1b);
                top2max(acc0[3], k0 + 1, m1b, m2b, i1b);
                top2max(acc1[0], k1,     m1a, m2a, i1a);
                top2max(acc1[1], k1 + 1, m1a, m2a, i1a);
                top2max(acc1[2], k1,     m1b, m2b, i1b);
                top2max(acc1[3], k1 + 1, m1b, m2b, i1b);
            }

            // quad reduce (lanes xor 1, 2), lexicographic (max v, min k)
            #pragma unroll
            for (int m = 1; m <= 2; m <<= 1) {
                float ov = __shfl_xor_sync(0xffffffffu, m1a, m);
                int   oi = __shfl_xor_sync(0xffffffffu, i1a, m);
                float o2 = __shfl_xor_sync(0xffffffffu, m2a, m);
                bool take = (ov > m1a) || (ov == m1a && oi < i1a);
                float nm2 = take ? fmaxf(m1a, o2) : fmaxf(m2a, ov);
                if (take) { m1a = ov; i1a = oi; }
                m2a = nm2;
                ov = __shfl_xor_sync(0xffffffffu, m1b, m);
                oi = __shfl_xor_sync(0xffffffffu, i1b, m);
                o2 = __shfl_xor_sync(0xffffffffu, m2b, m);
                take = (ov > m1b) || (ov == m1b && oi < i1b);
                nm2 = take ? fmaxf(m1b, o2) : fmaxf(m2b, ov);
                if (take) { m1b = ov; i1b = oi; }
                m2b = nm2;
            }
            if (l4 == 0) {
                const int r0 = m0 + lg, r1 = r0 + 8;
                s_win[r0] = i1a;
                if (!(m1a - m2a > MARGIN_V)) { int q = atomicAdd(s_qn, 1); s_que[q] = r0; }
                s_win[r1] = i1b;
                if (!(m1b - m2b > MARGIN_V)) { int q = atomicAdd(s_qn, 1); s_que[q] = r1; }
            }
        }
        __syncthreads();

        // ---- Phase E: exact rescore (reference chain) for ambiguous tokens ----
        {
            const int nq = *s_qn;
            for (int j = 0; j < nq; j++) {
                const int tt = s_que[j];
                const float x2t = s_x2[tt];
                float xr[DD];
                #pragma unroll
                for (int d = 0; d < DD; d++)
                    xr[d] = __ldg(xb + (long long)d * TT + tt);
                float bd; int bk;
                {
                    const int k0 = tid, k1 = tid + 256;
                    const float4* e0 = (const float4*)(emb + k0 * DD);
                    const float4* e1 = (const float4*)(emb + k1 * DD);
                    float s0 = 0.0f, s1 = 0.0f;
                    #pragma unroll
                    for (int g = 0; g < DD / 4; g++) {
                        float4 v0 = __ldg(e0 + g);
                        float4 v1 = __ldg(e1 + g);
                        s0 = fmaf(xr[g*4+0], v0.x, s0); s0 = fmaf(xr[g*4+1], v0.y, s0);
                        s0 = fmaf(xr[g*4+2], v0.z, s0); s0 = fmaf(xr[g*4+3], v0.w, s0);
                        s1 = fmaf(xr[g*4+0], v1.x, s1); s1 = fmaf(xr[g*4+1], v1.y, s1);
                        s1 = fmaf(xr[g*4+2], v1.z, s1); s1 = fmaf(xr[g*4+3], v1.w, s1);
                    }
                    float dA = __fadd_rn(__fsub_rn(x2t, 2.0f * s0), s_e2[k0]);
                    float dB = __fadd_rn(__fsub_rn(x2t, 2.0f * s1), s_e2[k1]);
                    bd = dA; bk = k0;
                    if (dB < bd) { bd = dB; bk = k1; }
                }
                #pragma unroll
                for (int off = 16; off; off >>= 1) {
                    float od = __shfl_down_sync(0xFFFFFFFFu, bd, off);
                    int   ok = __shfl_down_sync(0xFFFFFFFFu, bk, off);
                    if (od < bd || (od == bd && ok < bk)) { bd = od; bk = ok; }
                }
                if (lane == 0) { s_redf[wid] = bd; s_redk[wid] = bk; }
                __syncthreads();
                if (tid == 0) {
                    float fb = s_redf[0]; int fk = s_redk[0];
                    #pragma unroll
                    for (int w = 1; w < 8; w++) {
                        float od = s_redf[w]; int ok = s_redk[w];
                        if (od < fb || (od == fb && ok < fk)) { fb = od; fk = ok; }
                    }
                    s_win[tt] = fk;
                }
                __syncthreads();
            }
        }

        // ---- Phase F: gather q rows (overlay A region), coalesced writes ----
        if (tid < TILE_M) {
            const int tt = tid;
            const int k = s_win[tt];
            const float4* er = (const float4*)(emb + k * DD);
            #pragma unroll
            for (int g = 0; g < DD / 4; g++) {
                float4 v = __ldg(er + g);
                q_s[(g*4+0) * TILE_M + tt] = v.x;
                q_s[(g*4+1) * TILE_M + tt] = v.y;
                q_s[(g*4+2) * TILE_M + tt] = v.z;
                q_s[(g*4+3) * TILE_M + tt] = v.w;
            }
        }
        __syncthreads();
        {
            #pragma unroll
            for (int it = 0; it < (DD * TILE_M / 2) / NTHREADS; it++) {
                const int item = tid + it * NTHREADS;
                const int d = item >> 6;
                const int p = item & 63;
                const int ti = p * 2;
                float q0 = q_s[d * TILE_M + ti];
                float q1 = q_s[d * TILE_M + ti + 1];
                const float2 xv = *(const float2*)(xb + (long long)d * TT + ti);
                float2 stv = make_float2(__fadd_rn(xv.x, __fsub_rn(q0, xv.x)),
                                         __fadd_rn(xv.y, __fsub_rn(q1, xv.y)));
                float2 qv = make_float2(q0, q1);
                const long long o = obase + (long long)d * TT + t0 + ti;
                *(float2*)(o_st + o) = stv;
                *(float2*)(o_q + o)  = qv;
            }
        }
        __syncthreads();
    }
}

extern "C" void kernel_launch(void* const* d_in, const int* in_sizes, int n_in,
                              void* d_out, int out_size) {
    const float* x   = (const float*)d_in[0];
    const float* emb = (const float*)d_in[1];
    float* out = (float*)d_out;
    (void)in_sizes; (void)n_in; (void)out_size;

    cudaFuncSetAttribute(vq_tf32_kernel,
                         cudaFuncAttributeMaxDynamicSharedMemorySize, SMEM_TOTAL);
    vq_tf32_kernel<<<GRIDX, NTHREADS, SMEM_TOTAL>>>(x, emb, out);
}

// round 9
// speedup vs baseline: 1.0419x; 1.0419x over previous
#include <cuda_runtime.h>
#include <cuda_bf16.h>
#include <cstdint>

// VectorQuantizer via mma.sync (HMMA bf16, split-precision) + exact-margin rescore.
// R9: 3 independent accumulator chains (depth 4) + controlled unrolling.
// B=32, D=64, T=8192, K=512.

#define BB 32
#define DD 64
#define TT 8192
#define KK 512
#define NTOK (BB * TT)
#define TILE_M 128
#define NTILES (NTOK / TILE_M)      // 2048
#define TILES_PER_B (TT / TILE_M)   // 64
#define NTHREADS 256
#define GRIDX 152
#define ARRSZ ((long long)BB * DD * TT)
#define MARGIN 5e-5f
#define FINF 3.402823466e38f

// bf16 row stride: 72 elems = 144 bytes (conflict-free ldmatrix)
#define ROWS72 72
#define RSTRIDE (ROWS72 * 2)

// smem byte offsets
#define OFF_QN     0
#define OFF_REDF   32       // 8 f
#define OFF_REDK   64       // 8 i
#define OFF_E2     128      // 512 f -> 2176
#define OFF_X2     2176     // 128 f -> 2688
#define OFF_WIN    2688     // 128 i -> 3200
#define OFF_QUE    3200     // 128 i -> 3712
#define OFF_XS     3712     // 128*65*4 = 33280 -> 36992
#define OFF_XH     36992    // 128*144 = 18432 -> 55424
#define OFF_XL     55424    // 18432 -> 73856
#define OFF_QS     OFF_XH   // overlay: 64*128*4 = 32768 <= 36864 (XH+XL)
#define OFF_EH     73856    // 512*144 = 73728 -> 147584
#define OFF_EL     147584   // 73728 -> 221312
#define SMEM_TOTAL 221312
#define XS_STRIDE  65

__device__ __forceinline__ uint32_t smem_u32(const void* p) {
    uint32_t a;
    asm("{ .reg .u64 t; cvta.to.shared.u64 t, %1; cvt.u32.u64 %0, t; }" : "=r"(a) : "l"(p));
    return a;
}
__device__ __forceinline__ void ldsm_x4(uint32_t& r0, uint32_t& r1, uint32_t& r2, uint32_t& r3,
                                        uint32_t addr) {
    asm volatile("ldmatrix.sync.aligned.m8n8.x4.shared.b16 {%0,%1,%2,%3}, [%4];"
                 : "=r"(r0), "=r"(r1), "=r"(r2), "=r"(r3) : "r"(addr));
}
__device__ __forceinline__ void mma_bf16(float* c, const uint32_t* a, uint32_t b0, uint32_t b1) {
    asm volatile("mma.sync.aligned.m16n8k16.row.col.f32.bf16.bf16.f32 "
                 "{%0,%1,%2,%3}, {%4,%5,%6,%7}, {%8,%9}, {%0,%1,%2,%3};"
                 : "+f"(c[0]), "+f"(c[1]), "+f"(c[2]), "+f"(c[3])
                 : "r"(a[0]), "r"(a[1]), "r"(a[2]), "r"(a[3]), "r"(b0), "r"(b1));
}
__device__ __forceinline__ uint32_t pack_hi2(float v0, float v1, float& r0, float& r1) {
    __nv_bfloat16 h0 = __float2bfloat16_rn(v0);
    __nv_bfloat16 h1 = __float2bfloat16_rn(v1);
    r0 = __fsub_rn(v0, __bfloat162float(h0));
    r1 = __fsub_rn(v1, __bfloat162float(h1));
    return (uint32_t)__bfloat16_as_ushort(h0) | ((uint32_t)__bfloat16_as_ushort(h1) << 16);
}
__device__ __forceinline__ uint32_t pack_lo2(float r0, float r1) {
    __nv_bfloat16 l0 = __float2bfloat16_rn(r0);
    __nv_bfloat16 l1 = __float2bfloat16_rn(r1);
    return (uint32_t)__bfloat16_as_ushort(l0) | ((uint32_t)__bfloat16_as_ushort(l1) << 16);
}
__device__ __forceinline__ void top2(float dd, int k, float& d1, float& d2, int& i1) {
    if (dd < d1) { d2 = d1; d1 = dd; i1 = k; }
    else if (dd < d2) { d2 = dd; }
}

extern __shared__ __align__(1024) char smem[];

__global__ void __launch_bounds__(NTHREADS, 1)
vq_mma_kernel(const float* __restrict__ x,
              const float* __restrict__ emb,
              float* __restrict__ out) {
    const int tid  = threadIdx.x;
    const int wid  = tid >> 5;
    const int lane = tid & 31;
    const uint32_t sb = smem_u32(smem);

    float* s_e2   = (float*)(smem + OFF_E2);
    float* s_x2   = (float*)(smem + OFF_X2);
    int*   s_win  = (int*)(smem + OFF_WIN);
    int*   s_que  = (int*)(smem + OFF_QUE);
    float* s_xs   = (float*)(smem + OFF_XS);
    float* s_redf = (float*)(smem + OFF_REDF);
    int*   s_redk = (int*)(smem + OFF_REDK);
    int*   s_qn   = (int*)(smem + OFF_QN);
    float* q_s    = (float*)(smem + OFF_QS);

    // ---- Prologue: codebook -> exact e2 chain + bf16 split rows [512][72] ----
    for (int r = tid; r < KK; r += NTHREADS) {
        float ev[DD];
        const float4* er = (const float4*)(emb + r * DD);
        #pragma unroll
        for (int g = 0; g < DD / 4; g++) {
            float4 v = er[g];
            ev[g*4+0] = v.x; ev[g*4+1] = v.y; ev[g*4+2] = v.z; ev[g*4+3] = v.w;
        }
        float s = 0.0f;
        #pragma unroll
        for (int d = 0; d < DD; d++) s = __fadd_rn(s, __fmul_rn(ev[d], ev[d]));
        s_e2[r] = s;
        #pragma unroll
        for (int d = 0; d < DD; d += 2) {
            float r0, r1;
            uint32_t hp = pack_hi2(ev[d], ev[d+1], r0, r1);
            uint32_t lp = pack_lo2(r0, r1);
            *(uint32_t*)(smem + OFF_EH + r * RSTRIDE + d * 2) = hp;
            *(uint32_t*)(smem + OFF_EL + r * RSTRIDE + d * 2) = lp;
        }
    }

    float* o_st = out;
    float* o_q  = out + ARRSZ;

    const int lane4 = lane & 3;
    const int laneg = lane >> 2;
    const uint32_t a_off = (uint32_t)((lane & 15) * RSTRIDE + (lane >> 4) * 16);
    const uint32_t b_off = (uint32_t)((((lane & 7) + ((lane >> 4) << 3)) * RSTRIDE) +
                                      (((lane >> 3) & 1) * 16));

    for (int tile = blockIdx.x; tile < NTILES; tile += GRIDX) {
        const int b  = tile / TILES_PER_B;
        const int t0 = (tile % TILES_PER_B) * TILE_M;
        const float* xb = x + (long long)b * DD * TT + t0;
        const long long obase = (long long)b * DD * TT;

        // ---- Phase A: load x, stage f32, exact x2 chain, bf16 split rows ----
        if (tid == 0) *s_qn = 0;
        if (tid < TILE_M) {
            const int tt = tid;
            float xv[DD];
            #pragma unroll
            for (int d = 0; d < DD; d++) xv[d] = xb[(long long)d * TT + tt];
            float s = 0.0f;
            #pragma unroll
            for (int d = 0; d < DD; d++) {
                s_xs[tt * XS_STRIDE + d] = xv[d];
                s = __fadd_rn(s, __fmul_rn(xv[d], xv[d]));
            }
            s_x2[tt] = s;
            #pragma unroll
            for (int d = 0; d < DD; d += 2) {
                float r0, r1;
                uint32_t hp = pack_hi2(xv[d], xv[d+1], r0, r1);
                uint32_t lp = pack_lo2(r0, r1);
                *(uint32_t*)(smem + OFF_XH + tt * RSTRIDE + d * 2) = hp;
                *(uint32_t*)(smem + OFF_XL + tt * RSTRIDE + d * 2) = lp;
            }
        }
        __syncthreads();

        // ---- Phase B: screen. warp w: tokens [16w,16w+16), all 512 codes ----
        {
            const int m0 = wid * 16;
            uint32_t ah[4][4], al[4][4];
            const uint32_t abh = sb + OFF_XH + m0 * RSTRIDE + a_off;
            const uint32_t abl = sb + OFF_XL + m0 * RSTRIDE + a_off;
            #pragma unroll
            for (int s = 0; s < 4; s++) {
                ldsm_x4(ah[s][0], ah[s][1], ah[s][2], ah[s][3], abh + s * 32);
                ldsm_x4(al[s][0], al[s][1], al[s][2], al[s][3], abl + s * 32);
            }

            float d1a = FINF, d2a = FINF, d1b = FINF, d2b = FINF;
            int   i1a = 0, i1b = 0;
            const uint32_t bbh = sb + OFF_EH + b_off;
            const uint32_t bbl = sb + OFF_EL + b_off;

            #pragma unroll 1
            for (int c = 0; c < 8; c++) {
                const int n0 = c * 64;
                #pragma unroll 2
                for (int p = 0; p < 4; p++) {
                    // 3 independent chains: hh | hl | lh  (depth 4 each)
                    float hh[8], hl[8], lh[8];
                    #pragma unroll
                    for (int j = 0; j < 8; j++) { hh[j] = 0.f; hl[j] = 0.f; lh[j] = 0.f; }

                    const uint32_t bth = bbh + (uint32_t)((n0 + 16 * p) * RSTRIDE);
                    const uint32_t btl = bbl + (uint32_t)((n0 + 16 * p) * RSTRIDE);
                    #pragma unroll
                    for (int s = 0; s < 4; s++) {
                        uint32_t h0, h1, h2, h3, l0, l1, l2, l3;
                        ldsm_x4(h0, h1, h2, h3, bth + s * 32);
                        ldsm_x4(l0, l1, l2, l3, btl + s * 32);
                        mma_bf16(hh,     ah[s], h0, h1);
                        mma_bf16(hh + 4, ah[s], h2, h3);
                        mma_bf16(hl,     ah[s], l0, l1);
                        mma_bf16(hl + 4, ah[s], l2, l3);
                        mma_bf16(lh,     al[s], h0, h1);
                        mma_bf16(lh + 4, al[s], h2, h3);
                    }
                    const int cb0 = n0 + 16 * p + 2 * lane4;
                    const int cb1 = cb0 + 8;
                    const float e00 = s_e2[cb0], e01 = s_e2[cb0 + 1];
                    const float e10 = s_e2[cb1], e11 = s_e2[cb1 + 1];
                    float v;
                    v = __fadd_rn(__fadd_rn(hh[0], hl[0]), lh[0]);
                    top2(fmaf(-2.0f, v, e00), cb0,     d1a, d2a, i1a);
                    v = __fadd_rn(__fadd_rn(hh[1], hl[1]), lh[1]);
                    top2(fmaf(-2.0f, v, e01), cb0 + 1, d1a, d2a, i1a);
                    v = __fadd_rn(__fadd_rn(hh[2], hl[2]), lh[2]);
                    top2(fmaf(-2.0f, v, e00), cb0,     d1b, d2b, i1b);
                    v = __fadd_rn(__fadd_rn(hh[3], hl[3]), lh[3]);
                    top2(fmaf(-2.0f, v, e01), cb0 + 1, d1b, d2b, i1b);
                    v = __fadd_rn(__fadd_rn(hh[4], hl[4]), lh[4]);
                    top2(fmaf(-2.0f, v, e10), cb1,     d1a, d2a, i1a);
                    v = __fadd_rn(__fadd_rn(hh[5], hl[5]), lh[5]);
                    top2(fmaf(-2.0f, v, e11), cb1 + 1, d1a, d2a, i1a);
                    v = __fadd_rn(__fadd_rn(hh[6], hl[6]), lh[6]);
                    top2(fmaf(-2.0f, v, e10), cb1,     d1b, d2b, i1b);
                    v = __fadd_rn(__fadd_rn(hh[7], hl[7]), lh[7]);
                    top2(fmaf(-2.0f, v, e11), cb1 + 1, d1b, d2b, i1b);
                }
            }

            // quad reduce (lanes xor 1, 2) lexicographic (d, k)
            #pragma unroll
            for (int m = 1; m <= 2; m <<= 1) {
                float od = __shfl_xor_sync(0xffffffffu, d1a, m);
                int   oi = __shfl_xor_sync(0xffffffffu, i1a, m);
                float o2 = __shfl_xor_sync(0xffffffffu, d2a, m);
                bool take = (od < d1a) || (od == d1a && oi < i1a);
                float nd2 = take ? fminf(d1a, o2) : fminf(d2a, od);
                if (take) { d1a = od; i1a = oi; }
                d2a = nd2;
                od = __shfl_xor_sync(0xffffffffu, d1b, m);
                oi = __shfl_xor_sync(0xffffffffu, i1b, m);
                o2 = __shfl_xor_sync(0xffffffffu, d2b, m);
                take = (od < d1b) || (od == d1b && oi < i1b);
                nd2 = take ? fminf(d1b, o2) : fminf(d2b, od);
                if (take) { d1b = od; i1b = oi; }
                d2b = nd2;
            }
            if (lane4 == 0) {
                const int r0 = m0 + laneg, r1 = r0 + 8;
                s_win[r0] = i1a;
                if (!(d2a - d1a > MARGIN)) { int q = atomicAdd(s_qn, 1); s_que[q] = r0; }
                s_win[r1] = i1b;
                if (!(d2b - d1b > MARGIN)) { int q = atomicAdd(s_qn, 1); s_que[q] = r1; }
            }
        }
        __syncthreads();

        // ---- Phase E: exact rescore (reference chain) for ambiguous tokens ----
        {
            const int nq = *s_qn;
            for (int j = 0; j < nq; j++) {
                const int tt = s_que[j];
                const float x2t = s_x2[tt];
                float bd; int bk;
                {
                    const int k0 = tid, k1 = tid + 256;
                    const float4* e0 = (const float4*)(emb + k0 * DD);
                    const float4* e1 = (const float4*)(emb + k1 * DD);
                    float a0 = 0.0f, a1 = 0.0f;
                    #pragma unroll
                    for (int g = 0; g < DD / 4; g++) {
                        float4 v0 = __ldg(e0 + g);
                        float4 v1 = __ldg(e1 + g);
                        float p0 = s_xs[tt * XS_STRIDE + g*4 + 0];
                        float p1 = s_xs[tt * XS_STRIDE + g*4 + 1];
                        float p2 = s_xs[tt * XS_STRIDE + g*4 + 2];
                        float p3 = s_xs[tt * XS_STRIDE + g*4 + 3];
                        a0 = fmaf(p0, v0.x, a0); a0 = fmaf(p1, v0.y, a0);
                        a0 = fmaf(p2, v0.z, a0); a0 = fmaf(p3, v0.w, a0);
                        a1 = fmaf(p0, v1.x, a1); a1 = fmaf(p1, v1.y, a1);
                        a1 = fmaf(p2, v1.z, a1); a1 = fmaf(p3, v1.w, a1);
                    }
                    float dA = __fadd_rn(__fsub_rn(x2t, 2.0f * a0), s_e2[k0]);
                    float dB = __fadd_rn(__fsub_rn(x2t, 2.0f * a1), s_e2[k1]);
                    bd = dA; bk = k0;
                    if (dB < bd) { bd = dB; bk = k1; }
                }
                #pragma unroll
                for (int off = 16; off; off >>= 1) {
                    float od = __shfl_down_sync(0xFFFFFFFFu, bd, off);
                    int   ok = __shfl_down_sync(0xFFFFFFFFu, bk, off);
                    if (od < bd || (od == bd && ok < bk)) { bd = od; bk = ok; }
                }
                if (lane == 0) { s_redf[wid] = bd; s_redk[wid] = bk; }
                __syncthreads();
                if (tid == 0) {
                    float fb = s_redf[0]; int fk = s_redk[0];
                    #pragma unroll
                    for (int w = 1; w < 8; w++) {
                        float od = s_redf[w]; int ok = s_redk[w];
                        if (od < fb || (od == fb && ok < fk)) { fb = od; fk = ok; }
                    }
                    s_win[tt] = fk;
                }
                __syncthreads();
            }
        }

        // ---- Phase F: gather q rows (overlay XH/XL) then coalesced writes ----
        if (tid < TILE_M) {
            const int tt = tid;
            const int k = s_win[tt];
            const float4* er = (const float4*)(emb + k * DD);
            #pragma unroll
            for (int g = 0; g < DD / 4; g++) {
                float4 v = __ldg(er + g);
                q_s[(g*4+0) * 128 + tt] = v.x;
                q_s[(g*4+1) * 128 + tt] = v.y;
                q_s[(g*4+2) * 128 + tt] = v.z;
                q_s[(g*4+3) * 128 + tt] = v.w;
            }
        }
        __syncthreads();
        {
            #pragma unroll
            for (int it = 0; it < (64 * 64) / NTHREADS; it++) {
                const int item = tid + it * NTHREADS;
                const int d = item >> 6;
                const int p = item & 63;
                const int ti = p * 2;
                float q0 = q_s[d * 128 + ti];
                float q1 = q_s[d * 128 + ti + 1];
                float x0 = s_xs[ti * XS_STRIDE + d];
                float x1 = s_xs[(ti + 1) * XS_STRIDE + d];
                float2 stv = make_float2(__fadd_rn(x0, __fsub_rn(q0, x0)),
                                         __fadd_rn(x1, __fsub_rn(q1, x1)));
                float2 qv = make_float2(q0, q1);
                const long long o = obase + (long long)d * TT + t0 + ti;
                *(float2*)(o_st + o) = stv;
                *(float2*)(o_q + o)  = qv;
            }
        }
        __syncthreads();
    }
}

extern "C" void kernel_launch(void* const* d_in, const int* in_sizes, int n_in,
                              void* d_out, int out_size) {
    const float* x   = (const float*)d_in[0];
    const float* emb = (const float*)d_in[1];
    float* out = (float*)d_out;
    (void)in_sizes; (void)n_in; (void)out_size;

    cudaFuncSetAttribute(vq_mma_kernel,
                         cudaFuncAttributeMaxDynamicSharedMemorySize, SMEM_TOTAL);
    vq_mma_kernel<<<GRIDX, NTHREADS, SMEM_TOTAL>>>(x, emb, out);
}